// round 15
// baseline (speedup 1.0000x reference)
#include <cuda_runtime.h>
#include <cuda_bf16.h>
#include <cstdint>

#define BB    128
#define DDIM  262144             // 512*512
#define GRID  148                // 1 CTA per SM (co-residency required for handshake)
#define NTH   512                // 8 MMA warps + 8 producer warps
#define NT    (DDIM / 64)        // 4096 K-tiles of 64 fp32
#define TILE  16384              // 128 rows x 64 bf16 (128B/row)
#define STAGE (4 * TILE)         // Ahi, Alo, Bhi, Blo
#define SMEM_BYTES (2 * STAGE)   // 131072

__device__ float g_part[GRID * BB * BB];   // per-CTA GEMM partials (~9.7 MB)
__device__ float g_xn2p[GRID * BB];
__device__ float g_yn2p[GRID * BB];
__device__ float g_dots[BB * BB];
__device__ float g_xn2[BB];
__device__ float g_yn2[BB];
__device__ volatile int g_cnt1;
__device__ volatile int g_cnt2;

// ---------------- helpers (baseline PTX only; no sm_103a-specific ops) ----------------
__device__ __forceinline__ uint32_t smem_u32(const void* p) {
    uint32_t a;
    asm("{ .reg .u64 t; cvta.to.shared.u64 t, %1; cvt.u32.u64 %0, t; }" : "=r"(a) : "l"(p));
    return a;
}
__device__ __forceinline__ void ldsm4(uint32_t* r, uint32_t addr) {
    asm volatile("ldmatrix.sync.aligned.m8n8.x4.shared.b16 {%0,%1,%2,%3}, [%4];"
                 : "=r"(r[0]), "=r"(r[1]), "=r"(r[2]), "=r"(r[3]) : "r"(addr));
}
__device__ __forceinline__ void mma_bf16(float* d, const uint32_t* a, const uint32_t* b) {
    asm volatile("mma.sync.aligned.m16n8k16.row.col.f32.bf16.bf16.f32 "
                 "{%0,%1,%2,%3}, {%4,%5,%6,%7}, {%8,%9}, {%0,%1,%2,%3};"
                 : "+f"(d[0]), "+f"(d[1]), "+f"(d[2]), "+f"(d[3])
                 : "r"(a[0]), "r"(a[1]), "r"(a[2]), "r"(a[3]), "r"(b[0]), "r"(b[1]));
}
#define BAR_SYNC(id)   asm volatile("bar.sync %0, %1;"   :: "r"(id), "r"(NTH) : "memory")
#define BAR_ARRIVE(id) asm volatile("bar.arrive %0, %1;" :: "r"(id), "r"(NTH) : "memory")

// fp32 -> (bf16 hi by truncation, bf16 lo = RN(f - hi)); fuse sum of squares.
__device__ __forceinline__ void split_store(float4 a, char* hi, char* lo,
                                            uint32_t so, float& acc) {
    acc = fmaf(a.x, a.x, acc); acc = fmaf(a.y, a.y, acc);
    acc = fmaf(a.z, a.z, acc); acc = fmaf(a.w, a.w, acc);
    uint32_t bx = __float_as_uint(a.x), by = __float_as_uint(a.y);
    uint32_t bz = __float_as_uint(a.z), bw = __float_as_uint(a.w);
    uint32_t h0 = __byte_perm(bx, by, 0x7632);
    uint32_t h1 = __byte_perm(bz, bw, 0x7632);
    float lx = a.x - __uint_as_float(bx & 0xFFFF0000u);
    float ly = a.y - __uint_as_float(by & 0xFFFF0000u);
    float lz = a.z - __uint_as_float(bz & 0xFFFF0000u);
    float lw = a.w - __uint_as_float(bw & 0xFFFF0000u);
    uint32_t l0, l1;
    asm("cvt.rn.satfinite.bf16x2.f32 %0, %1, %2;" : "=r"(l0) : "f"(ly), "f"(lx));
    asm("cvt.rn.satfinite.bf16x2.f32 %0, %1, %2;" : "=r"(l1) : "f"(lw), "f"(lz));
    *reinterpret_cast<uint2*>(hi + so) = make_uint2(h0, h1);
    *reinterpret_cast<uint2*>(lo + so) = make_uint2(l0, l1);
}

// ------------- Fused: warp-specialized split-K GEMM + grid handshake + reduce + finalize -------------
__global__ void __launch_bounds__(NTH, 1)
fused_kernel(const float* __restrict__ Z, const float* __restrict__ Y,
             float* __restrict__ out) {
    extern __shared__ __align__(1024) char smem[];
    const uint32_t sb = smem_u32(smem);
    const int tid = threadIdx.x;
    const int bid = blockIdx.x;
    const int nit = (NT - bid + GRID - 1) / GRID;   // 27 or 28

    // =========================== phase 1: GEMM ===========================
    if (tid < 256) {
        // ---- consumers: LDSM + MMA ----
        const int w = tid >> 5;
        const int l = tid & 31;
        const uint32_t mbase = (uint32_t)(w & 3) * 32u;
        const uint32_t nbase = (uint32_t)(w >> 2) * 64u;
        const uint32_t sx    = (uint32_t)(l & 7);
        const uint32_t aoff  = (mbase + (uint32_t)(l & 15)) * 128u;
        const uint32_t chA   = (uint32_t)(l >> 4);
        const uint32_t boff  = (nbase + 8u * (uint32_t)(l >> 4) + (uint32_t)(l & 7)) * 128u;
        const uint32_t chB   = (uint32_t)((l >> 3) & 1);

        float acc[2][8][4];
#pragma unroll
        for (int mt = 0; mt < 2; ++mt)
#pragma unroll
            for (int nt = 0; nt < 8; ++nt)
#pragma unroll
                for (int c = 0; c < 4; ++c) acc[mt][nt][c] = 0.f;

        for (int it = 0; it < nit; ++it) {
            const int b = it & 1;
            BAR_SYNC(1 + b);                         // wait buffer filled
            const uint32_t stb = sb + (uint32_t)b * STAGE;
#pragma unroll
            for (int ks = 0; ks < 4; ++ks) {
                const uint32_t swA = 16u * (((uint32_t)(2 * ks) + chA) ^ sx);
                const uint32_t swB = 16u * (((uint32_t)(2 * ks) + chB) ^ sx);
                uint32_t ah0[4], ah1[4], al0[4], al1[4];
                ldsm4(ah0, stb + aoff + swA);
                ldsm4(ah1, stb + aoff + 2048u + swA);
                ldsm4(al0, stb + TILE + aoff + swA);
                ldsm4(al1, stb + TILE + aoff + 2048u + swA);
#pragma unroll
                for (int j = 0; j < 4; ++j) {
                    uint32_t bh[4], bl[4];
                    ldsm4(bh, stb + 2 * TILE + boff + (uint32_t)j * 2048u + swB);
                    ldsm4(bl, stb + 3 * TILE + boff + (uint32_t)j * 2048u + swB);
                    // round-11 proven ordering (chained per accumulator)
                    mma_bf16(acc[0][2 * j],     ah0, bh);
                    mma_bf16(acc[0][2 * j],     al0, bh);
                    mma_bf16(acc[0][2 * j],     ah0, bl);
                    mma_bf16(acc[0][2 * j + 1], ah0, bh + 2);
                    mma_bf16(acc[0][2 * j + 1], al0, bh + 2);
                    mma_bf16(acc[0][2 * j + 1], ah0, bl + 2);
                    mma_bf16(acc[1][2 * j],     ah1, bh);
                    mma_bf16(acc[1][2 * j],     al1, bh);
                    mma_bf16(acc[1][2 * j],     ah1, bl);
                    mma_bf16(acc[1][2 * j + 1], ah1, bh + 2);
                    mma_bf16(acc[1][2 * j + 1], al1, bh + 2);
                    mma_bf16(acc[1][2 * j + 1], ah1, bl + 2);
                }
            }
            BAR_ARRIVE(3 + b);                       // buffer consumed
        }

        // deterministic per-CTA partial write
        const int g  = l >> 2;
        const int t2 = (l & 3) * 2;
        float* gp = g_part + (size_t)bid * (BB * BB);
#pragma unroll
        for (int mt = 0; mt < 2; ++mt)
#pragma unroll
            for (int nt = 0; nt < 8; ++nt) {
                int m = (int)mbase + 16 * mt + g;
                int n = (int)nbase + 8 * nt + t2;
                *reinterpret_cast<float2*>(gp + m * BB + n) =
                    make_float2(acc[mt][nt][0], acc[mt][nt][1]);
                *reinterpret_cast<float2*>(gp + (m + 8) * BB + n) =
                    make_float2(acc[mt][nt][2], acc[mt][nt][3]);
            }
    } else {
        // ---- producers: LDG + convert + STS + norms ----
        const int ptid = tid - 256;
        const int l    = tid & 31;
        const int r0v  = ptid >> 4;          // 0..15
        const int c8   = ptid & 15;
        const uint32_t cvt_base = (uint32_t)r0v * 128u
                                + 16u * ((uint32_t)(c8 >> 1) ^ (uint32_t)(r0v & 7))
                                + 8u * (uint32_t)(c8 & 1);

        const float4* zb = reinterpret_cast<const float4*>(Z) + (size_t)r0v * (DDIM / 4) + c8;
        const float4* yb = reinterpret_cast<const float4*>(Y) + (size_t)r0v * (DDIM / 4) + c8;

        float az[8], ay[8];
#pragma unroll
        for (int k = 0; k < 8; ++k) { az[k] = 0.f; ay[k] = 0.f; }

        float4 vz[8], vy[8];
        int t = bid;
#pragma unroll
        for (int k = 0; k < 8; ++k) {
            size_t o = (size_t)k * 16 * (DDIM / 4) + (size_t)t * 16;
            vz[k] = zb[o]; vy[k] = yb[o];
        }

        for (int it = 0; it < nit; ++it) {
            const int b = it & 1;
            if (it >= 2) BAR_SYNC(3 + b);            // wait buffer free
            char* st = smem + b * STAGE;
#pragma unroll
            for (int k = 0; k < 8; ++k) {
                uint32_t so = cvt_base + (uint32_t)k * 2048u;
                split_store(vz[k], st,            st + TILE,     so, az[k]);  // Ahi, Alo
                split_store(vy[k], st + 2 * TILE, st + 3 * TILE, so, ay[k]);  // Bhi, Blo
            }
            BAR_ARRIVE(1 + b);                       // buffer filled
            const int tn = t + GRID;
            if (it + 1 < nit) {
#pragma unroll
                for (int k = 0; k < 8; ++k) {
                    size_t o = (size_t)k * 16 * (DDIM / 4) + (size_t)tn * 16;
                    vz[k] = zb[o]; vy[k] = yb[o];
                }
            }
            t = tn;
        }

        // norm partials: 16-lane row-slice reduction
#pragma unroll
        for (int k = 0; k < 8; ++k) {
            float a = az[k], c = ay[k];
#pragma unroll
            for (int m = 1; m < 16; m <<= 1) {
                a += __shfl_xor_sync(0xFFFFFFFFu, a, m);
                c += __shfl_xor_sync(0xFFFFFFFFu, c, m);
            }
            if ((l & 15) == 0) {
                int row = r0v + (k << 4);
                g_xn2p[bid * BB + row] = a;
                g_yn2p[bid * BB + row] = c;
            }
        }
    }

    // ================== phase 2: grid handshake (threadfence reduction) ==================
    __syncthreads();
    if (tid == 0) {
        __threadfence();
        atomicAdd((int*)&g_cnt1, 1);
    }
    if (bid >= BB) return;                 // CTAs 128..147 done

    if (tid == 0) {
        while (g_cnt1 != GRID) { __nanosleep(100); }
        __threadfence();
    }
    __syncthreads();

    // ================== phase 3: deterministic reduce (CTAs 0..127) ==================
    {
        float* sred = reinterpret_cast<float*>(smem);            // [4][BB]
        float* snx  = reinterpret_cast<float*>(smem) + 4 * BB;   // [4][BB]
        const int j = bid;
        const int i = tid & 127;
        const int q = tid >> 7;            // 0..3; 148 = 4*37
        const float* p = g_part + j * BB + i;
        float s = 0.f;
#pragma unroll 4
        for (int c = q * 37; c < q * 37 + 37; ++c) s += p[(size_t)c * (BB * BB)];
        sred[q * BB + i] = s;
        if (j < 2) {
            const float* np = (j == 0 ? g_xn2p : g_yn2p) + i;
            float a = 0.f;
#pragma unroll 4
            for (int c = q * 37; c < q * 37 + 37; ++c) a += np[c * BB];
            snx[q * BB + i] = a;
        }
        __syncthreads();
        if (q == 0) {
            g_dots[j * BB + i] = (sred[i] + sred[BB + i]) + (sred[2 * BB + i] + sred[3 * BB + i]);
            if (j == 0) g_xn2[i] = (snx[i] + snx[BB + i]) + (snx[2 * BB + i] + snx[3 * BB + i]);
            if (j == 1) g_yn2[i] = (snx[i] + snx[BB + i]) + (snx[2 * BB + i] + snx[3 * BB + i]);
        }
    }
    __syncthreads();
    if (tid == 0) {
        __threadfence();
        atomicAdd((int*)&g_cnt2, 1);
    }
    if (bid != 0) return;

    // ================== phase 4: finalize (CTA 0) ==================
    if (tid == 0) {
        while (g_cnt2 != BB) { __nanosleep(100); }
        __threadfence();
    }
    __syncthreads();
    {
        float* sxn = reinterpret_cast<float*>(smem);         // [BB]
        int* cnt   = reinterpret_cast<int*>(smem + 512);     // c1, c10
        const int i = tid;
        if (i == 0) { cnt[0] = 0; cnt[1] = 0; }
        if (i < BB) sxn[i] = sqrtf(g_xn2[i]);
        __syncthreads();
        if (i < BB) {
            const float yni = sqrtf(g_yn2[i]);
            const float d = g_dots[i * BB + i] / fmaxf(sxn[i] * yni, 1e-8f);
            int cgt = 0, ceq = 0;
#pragma unroll 8
            for (int j = 0; j < BB; ++j) {
                float s = g_dots[j * BB + i] / fmaxf(sxn[j] * yni, 1e-8f);
                cgt += (s > d) ? 1 : 0;
                ceq += (s == d && j < i) ? 1 : 0;   // stable tie-break: lower index wins
            }
            const int rank = cgt + ceq;
            atomicAdd(&cnt[0], (rank == 0) ? 1 : 0);
            atomicAdd(&cnt[1], (rank < 10) ? 1 : 0);
        }
        __syncthreads();
        if (i == 0) {
            out[0] = (float)cnt[0] / (float)BB;
            out[1] = (float)cnt[1] / (float)BB;
            g_cnt1 = 0;                  // reset for next graph replay
            g_cnt2 = 0;
            __threadfence();
        }
    }
}

extern "C" void kernel_launch(void* const* d_in, const int* in_sizes, int n_in,
                              void* d_out, int out_size) {
    const float* Z = (const float*)d_in[0];
    const float* Y = (const float*)d_in[1];
    float* out = (float*)d_out;
    cudaFuncSetAttribute(fused_kernel, cudaFuncAttributeMaxDynamicSharedMemorySize, SMEM_BYTES);
    fused_kernel<<<GRID, NTH, SMEM_BYTES>>>(Z, Y, out);
}

// round 16
// speedup vs baseline: 1.4327x; 1.4327x over previous
#include <cuda_runtime.h>
#include <cuda_bf16.h>
#include <cstdint>

#define BB    128
#define DDIM  262144             // 512*512
#define GRID  148                // 1 CTA per SM
#define NTH   512                // 8 MMA warps + 8 producer warps
#define NT    (DDIM / 64)        // 4096 K-tiles of 64 fp32
#define TILE  16384              // 128 rows x 64 bf16 (128B/row)
#define STAGE (4 * TILE)         // Ahi, Alo, Bhi, Blo
#define SMEM_BYTES (2 * STAGE)   // 131072

__device__ float g_part[GRID * BB * BB];   // per-CTA partials, TRANSPOSED: [c][n][m] (n=Y idx, m=Z idx)
__device__ float g_xn2p[GRID * BB];
__device__ float g_yn2p[GRID * BB];
__device__ unsigned int g_pack;            // done<<20 | top10<<10 | top1

// ---------------- helpers (baseline PTX only) ----------------
__device__ __forceinline__ uint32_t smem_u32(const void* p) {
    uint32_t a;
    asm("{ .reg .u64 t; cvta.to.shared.u64 t, %1; cvt.u32.u64 %0, t; }" : "=r"(a) : "l"(p));
    return a;
}
__device__ __forceinline__ void ldsm4(uint32_t* r, uint32_t addr) {
    asm volatile("ldmatrix.sync.aligned.m8n8.x4.shared.b16 {%0,%1,%2,%3}, [%4];"
                 : "=r"(r[0]), "=r"(r[1]), "=r"(r[2]), "=r"(r[3]) : "r"(addr));
}
__device__ __forceinline__ void mma_bf16(float* d, const uint32_t* a, const uint32_t* b) {
    asm volatile("mma.sync.aligned.m16n8k16.row.col.f32.bf16.bf16.f32 "
                 "{%0,%1,%2,%3}, {%4,%5,%6,%7}, {%8,%9}, {%0,%1,%2,%3};"
                 : "+f"(d[0]), "+f"(d[1]), "+f"(d[2]), "+f"(d[3])
                 : "r"(a[0]), "r"(a[1]), "r"(a[2]), "r"(a[3]), "r"(b[0]), "r"(b[1]));
}
#define BAR_SYNC(id)   asm volatile("bar.sync %0, %1;"   :: "r"(id), "r"(NTH) : "memory")
#define BAR_ARRIVE(id) asm volatile("bar.arrive %0, %1;" :: "r"(id), "r"(NTH) : "memory")

// fp32 -> (bf16 hi by truncation, bf16 lo = RN(f - hi)); fuse sum of squares.
__device__ __forceinline__ void split_store(float4 a, char* hi, char* lo,
                                            uint32_t so, float& acc) {
    acc = fmaf(a.x, a.x, acc); acc = fmaf(a.y, a.y, acc);
    acc = fmaf(a.z, a.z, acc); acc = fmaf(a.w, a.w, acc);
    uint32_t bx = __float_as_uint(a.x), by = __float_as_uint(a.y);
    uint32_t bz = __float_as_uint(a.z), bw = __float_as_uint(a.w);
    uint32_t h0 = __byte_perm(bx, by, 0x7632);
    uint32_t h1 = __byte_perm(bz, bw, 0x7632);
    float lx = a.x - __uint_as_float(bx & 0xFFFF0000u);
    float ly = a.y - __uint_as_float(by & 0xFFFF0000u);
    float lz = a.z - __uint_as_float(bz & 0xFFFF0000u);
    float lw = a.w - __uint_as_float(bw & 0xFFFF0000u);
    uint32_t l0, l1;
    asm("cvt.rn.satfinite.bf16x2.f32 %0, %1, %2;" : "=r"(l0) : "f"(ly), "f"(lx));
    asm("cvt.rn.satfinite.bf16x2.f32 %0, %1, %2;" : "=r"(l1) : "f"(lw), "f"(lz));
    *reinterpret_cast<uint2*>(hi + so) = make_uint2(h0, h1);
    *reinterpret_cast<uint2*>(lo + so) = make_uint2(l0, l1);
}

// ------------- GEMM: warp-specialized split-K (r11 hot loop, verbatim) -------------
__global__ void __launch_bounds__(NTH, 1)
gemm_kernel(const float* __restrict__ Z, const float* __restrict__ Y) {
    extern __shared__ __align__(1024) char smem[];
    const uint32_t sb = smem_u32(smem);
    const int tid = threadIdx.x;
    const int bid = blockIdx.x;
    const int nit = (NT - bid + GRID - 1) / GRID;   // 27 or 28

    // consumer tile coords needed again in the epilogue
    const int w = tid >> 5;
    const int l = tid & 31;
    const uint32_t mbase = (uint32_t)(w & 3) * 32u;
    const uint32_t nbase = (uint32_t)(w >> 2) * 64u;

    float acc[2][8][4];

    if (tid < 256) {
        // ---- consumers: LDSM + MMA ----
        const uint32_t sx    = (uint32_t)(l & 7);
        const uint32_t aoff  = (mbase + (uint32_t)(l & 15)) * 128u;
        const uint32_t chA   = (uint32_t)(l >> 4);
        const uint32_t boff  = (nbase + 8u * (uint32_t)(l >> 4) + (uint32_t)(l & 7)) * 128u;
        const uint32_t chB   = (uint32_t)((l >> 3) & 1);

#pragma unroll
        for (int mt = 0; mt < 2; ++mt)
#pragma unroll
            for (int nt = 0; nt < 8; ++nt)
#pragma unroll
                for (int c = 0; c < 4; ++c) acc[mt][nt][c] = 0.f;

        for (int it = 0; it < nit; ++it) {
            const int b = it & 1;
            BAR_SYNC(1 + b);                         // wait buffer filled
            const uint32_t stb = sb + (uint32_t)b * STAGE;
#pragma unroll
            for (int ks = 0; ks < 4; ++ks) {
                const uint32_t swA = 16u * (((uint32_t)(2 * ks) + chA) ^ sx);
                const uint32_t swB = 16u * (((uint32_t)(2 * ks) + chB) ^ sx);
                uint32_t ah0[4], ah1[4], al0[4], al1[4];
                ldsm4(ah0, stb + aoff + swA);
                ldsm4(ah1, stb + aoff + 2048u + swA);
                ldsm4(al0, stb + TILE + aoff + swA);
                ldsm4(al1, stb + TILE + aoff + 2048u + swA);
#pragma unroll
                for (int j = 0; j < 4; ++j) {
                    uint32_t bh[4], bl[4];
                    ldsm4(bh, stb + 2 * TILE + boff + (uint32_t)j * 2048u + swB);
                    ldsm4(bl, stb + 3 * TILE + boff + (uint32_t)j * 2048u + swB);
                    mma_bf16(acc[0][2 * j],     ah0, bh);
                    mma_bf16(acc[0][2 * j],     al0, bh);
                    mma_bf16(acc[0][2 * j],     ah0, bl);
                    mma_bf16(acc[0][2 * j + 1], ah0, bh + 2);
                    mma_bf16(acc[0][2 * j + 1], al0, bh + 2);
                    mma_bf16(acc[0][2 * j + 1], ah0, bl + 2);
                    mma_bf16(acc[1][2 * j],     ah1, bh);
                    mma_bf16(acc[1][2 * j],     al1, bh);
                    mma_bf16(acc[1][2 * j],     ah1, bl);
                    mma_bf16(acc[1][2 * j + 1], ah1, bh + 2);
                    mma_bf16(acc[1][2 * j + 1], al1, bh + 2);
                    mma_bf16(acc[1][2 * j + 1], ah1, bl + 2);
                }
            }
            BAR_ARRIVE(3 + b);                       // buffer consumed
        }
    } else {
        // ---- producers: LDG + convert + STS + norms ----
        const int ptid = tid - 256;
        const int r0v  = ptid >> 4;          // 0..15
        const int c8   = ptid & 15;
        const uint32_t cvt_base = (uint32_t)r0v * 128u
                                + 16u * ((uint32_t)(c8 >> 1) ^ (uint32_t)(r0v & 7))
                                + 8u * (uint32_t)(c8 & 1);

        const float4* zb = reinterpret_cast<const float4*>(Z) + (size_t)r0v * (DDIM / 4) + c8;
        const float4* yb = reinterpret_cast<const float4*>(Y) + (size_t)r0v * (DDIM / 4) + c8;

        float az[8], ay[8];
#pragma unroll
        for (int k = 0; k < 8; ++k) { az[k] = 0.f; ay[k] = 0.f; }

        float4 vz[8], vy[8];
        int t = bid;
#pragma unroll
        for (int k = 0; k < 8; ++k) {
            size_t o = (size_t)k * 16 * (DDIM / 4) + (size_t)t * 16;
            vz[k] = zb[o]; vy[k] = yb[o];
        }

        for (int it = 0; it < nit; ++it) {
            const int b = it & 1;
            if (it >= 2) BAR_SYNC(3 + b);            // wait buffer free
            char* st = smem + b * STAGE;
#pragma unroll
            for (int k = 0; k < 8; ++k) {
                uint32_t so = cvt_base + (uint32_t)k * 2048u;
                split_store(vz[k], st,            st + TILE,     so, az[k]);  // Ahi, Alo
                split_store(vy[k], st + 2 * TILE, st + 3 * TILE, so, ay[k]);  // Bhi, Blo
            }
            BAR_ARRIVE(1 + b);                       // buffer filled
            const int tn = t + GRID;
            if (it + 1 < nit) {
#pragma unroll
                for (int k = 0; k < 8; ++k) {
                    size_t o = (size_t)k * 16 * (DDIM / 4) + (size_t)tn * 16;
                    vz[k] = zb[o]; vy[k] = yb[o];
                }
            }
            t = tn;
        }

        // norm partials: 16-lane row-slice reduction, layout [c][row]
#pragma unroll
        for (int k = 0; k < 8; ++k) {
            float a = az[k], c = ay[k];
#pragma unroll
            for (int m = 1; m < 16; m <<= 1) {
                a += __shfl_xor_sync(0xFFFFFFFFu, a, m);
                c += __shfl_xor_sync(0xFFFFFFFFu, c, m);
            }
            if ((l & 15) == 0) {
                int row = r0v + (k << 4);
                g_xn2p[bid * BB + row] = a;
                g_yn2p[bid * BB + row] = c;
            }
        }
    }

    // ---- epilogue: stage acc in smem, write TRANSPOSED partial coalesced ----
    __syncthreads();                                  // stages dead; reuse smem
    float* sf = reinterpret_cast<float*>(smem);       // [128][129]
    if (tid < 256) {
        const int g  = l >> 2;
        const int t2 = (l & 3) * 2;
#pragma unroll
        for (int mt = 0; mt < 2; ++mt)
#pragma unroll
            for (int nt = 0; nt < 8; ++nt) {
                int m = (int)mbase + 16 * mt + g;
                int n = (int)nbase + 8 * nt + t2;
                sf[m * 129 + n]       = acc[mt][nt][0];
                sf[m * 129 + n + 1]   = acc[mt][nt][1];
                sf[(m + 8) * 129 + n]     = acc[mt][nt][2];
                sf[(m + 8) * 129 + n + 1] = acc[mt][nt][3];
            }
    }
    __syncthreads();
    float* gp = g_part + (size_t)bid * (BB * BB);
    for (int idx = tid; idx < BB * BB; idx += NTH) {
        int n = idx >> 7, m = idx & 127;              // gp[n*128+m] = dots[m][n] (m=Z,n=Y)
        gp[idx] = sf[m * 129 + n];
    }
}

// -------- reduce + finalize, fully parallel (128 CTAs), deterministic --------
__global__ void __launch_bounds__(512, 1)
reduce_finalize_kernel(float* __restrict__ out) {
    __shared__ float sd[4][BB];
    __shared__ float sxp[4][BB];
    __shared__ float syp[4][BB];
    __shared__ float sdot[BB];
    __shared__ float sxn[BB];
    __shared__ float syn2[BB];
    __shared__ int scnt[2];

    const int i = blockIdx.x;          // sim.T row (Y index)
    const int m = threadIdx.x & 127;   // column (Z index)
    const int q = threadIdx.x >> 7;    // 0..3; 148 = 4*37
    if (threadIdx.x == 0) { scnt[0] = 0; scnt[1] = 0; }

    float s = 0.f, a = 0.f, b = 0.f;
    const int c0 = q * 37;
#pragma unroll 4
    for (int c = c0; c < c0 + 37; ++c) {
        s += g_part[(size_t)c * (BB * BB) + i * BB + m];   // coalesced: m contiguous
        a += g_xn2p[c * BB + m];
        b += g_yn2p[c * BB + m];
    }
    sd[q][m] = s; sxp[q][m] = a; syp[q][m] = b;
    __syncthreads();

    if (q == 0) {
        sdot[m] = (sd[0][m] + sd[1][m]) + (sd[2][m] + sd[3][m]);
        sxn[m]  = sqrtf((sxp[0][m] + sxp[1][m]) + (sxp[2][m] + sxp[3][m]));
        syn2[m] = (syp[0][m] + syp[1][m]) + (syp[2][m] + syp[3][m]);
    }
    __syncthreads();

    if (q == 0) {
        const float yni = sqrtf(syn2[i]);
        const float d   = sdot[i] / fmaxf(sxn[i] * yni, 1e-8f);
        const float smv = sdot[m] / fmaxf(sxn[m] * yni, 1e-8f);
        int gt = (smv > d) ? 1 : 0;
        int eq = (smv == d && m < i) ? 1 : 0;    // stable tie-break: lower index wins
        // warp-level popcount, then smem combine (integers -> deterministic)
        unsigned bgt = __ballot_sync(0xFFFFFFFFu, gt != 0);
        unsigned beq = __ballot_sync(0xFFFFFFFFu, eq != 0);
        if ((threadIdx.x & 31) == 0) {
            atomicAdd(&scnt[0], __popc(bgt));
            atomicAdd(&scnt[1], __popc(beq));
        }
    }
    __syncthreads();

    if (threadIdx.x == 0) {
        const int rank = scnt[0] + scnt[1];
        const unsigned add = (1u << 20) | ((rank < 10 ? 1u : 0u) << 10) | (rank == 0 ? 1u : 0u);
        const unsigned old = atomicAdd(&g_pack, add);
        if ((old >> 20) == (unsigned)(BB - 1)) {     // last CTA finalizes
            const unsigned tot = old + add;
            out[0] = (float)(tot & 1023u) / (float)BB;
            out[1] = (float)((tot >> 10) & 1023u) / (float)BB;
            g_pack = 0;                              // reset for next graph replay
        }
    }
}

extern "C" void kernel_launch(void* const* d_in, const int* in_sizes, int n_in,
                              void* d_out, int out_size) {
    const float* Z = (const float*)d_in[0];
    const float* Y = (const float*)d_in[1];
    float* out = (float*)d_out;
    cudaFuncSetAttribute(gemm_kernel, cudaFuncAttributeMaxDynamicSharedMemorySize, SMEM_BYTES);
    gemm_kernel<<<GRID, NTH, SMEM_BYTES>>>(Z, Y);
    reduce_finalize_kernel<<<BB, 512>>>(out);
}

// round 17
// speedup vs baseline: 1.4629x; 1.0211x over previous
#include <cuda_runtime.h>
#include <cuda_bf16.h>
#include <cstdint>

#define BB    128
#define DDIM  262144             // 512*512
#define GRID  148                // 1 CTA per SM
#define NTH   512                // 8 MMA warps + 8 producer warps
#define NT    (DDIM / 64)        // 4096 K-tiles of 64 fp32
#define TILE  16384              // 128 rows x 64 bf16 (128B/row)
#define STAGE (4 * TILE)         // Ahi, Alo, Bhi, Blo
#define SMEM_BYTES (2 * STAGE)   // 131072

__device__ float g_part[GRID * BB * BB];   // per-CTA partials, TRANSPOSED: [c][n][m] (n=Y idx, m=Z idx)
__device__ float g_xn2p[GRID * BB];
__device__ float g_yn2p[GRID * BB];
__device__ unsigned int g_pack;            // done<<20 | top10<<10 | top1

// ---------------- helpers (baseline PTX only) ----------------
__device__ __forceinline__ uint32_t smem_u32(const void* p) {
    uint32_t a;
    asm("{ .reg .u64 t; cvta.to.shared.u64 t, %1; cvt.u32.u64 %0, t; }" : "=r"(a) : "l"(p));
    return a;
}
__device__ __forceinline__ void ldsm4(uint32_t* r, uint32_t addr) {
    asm volatile("ldmatrix.sync.aligned.m8n8.x4.shared.b16 {%0,%1,%2,%3}, [%4];"
                 : "=r"(r[0]), "=r"(r[1]), "=r"(r[2]), "=r"(r[3]) : "r"(addr));
}
__device__ __forceinline__ void mma_bf16(float* d, const uint32_t* a, const uint32_t* b) {
    asm volatile("mma.sync.aligned.m16n8k16.row.col.f32.bf16.bf16.f32 "
                 "{%0,%1,%2,%3}, {%4,%5,%6,%7}, {%8,%9}, {%0,%1,%2,%3};"
                 : "+f"(d[0]), "+f"(d[1]), "+f"(d[2]), "+f"(d[3])
                 : "r"(a[0]), "r"(a[1]), "r"(a[2]), "r"(a[3]), "r"(b[0]), "r"(b[1]));
}
#define BAR_SYNC(id)   asm volatile("bar.sync %0, %1;"   :: "r"(id), "r"(NTH) : "memory")
#define BAR_ARRIVE(id) asm volatile("bar.arrive %0, %1;" :: "r"(id), "r"(NTH) : "memory")

// fp32 -> (bf16 hi by truncation, bf16 lo = RN(f - hi)); fuse sum of squares.
__device__ __forceinline__ void split_store(float4 a, char* hi, char* lo,
                                            uint32_t so, float& acc) {
    acc = fmaf(a.x, a.x, acc); acc = fmaf(a.y, a.y, acc);
    acc = fmaf(a.z, a.z, acc); acc = fmaf(a.w, a.w, acc);
    uint32_t bx = __float_as_uint(a.x), by = __float_as_uint(a.y);
    uint32_t bz = __float_as_uint(a.z), bw = __float_as_uint(a.w);
    uint32_t h0 = __byte_perm(bx, by, 0x7632);
    uint32_t h1 = __byte_perm(bz, bw, 0x7632);
    float lx = a.x - __uint_as_float(bx & 0xFFFF0000u);
    float ly = a.y - __uint_as_float(by & 0xFFFF0000u);
    float lz = a.z - __uint_as_float(bz & 0xFFFF0000u);
    float lw = a.w - __uint_as_float(bw & 0xFFFF0000u);
    uint32_t l0, l1;
    asm("cvt.rn.satfinite.bf16x2.f32 %0, %1, %2;" : "=r"(l0) : "f"(ly), "f"(lx));
    asm("cvt.rn.satfinite.bf16x2.f32 %0, %1, %2;" : "=r"(l1) : "f"(lw), "f"(lz));
    *reinterpret_cast<uint2*>(hi + so) = make_uint2(h0, h1);
    *reinterpret_cast<uint2*>(lo + so) = make_uint2(l0, l1);
}

// ------------- GEMM: warp-specialized split-K; MMAs interleaved (RAW dist 1 -> 4) -------------
__global__ void __launch_bounds__(NTH, 1)
gemm_kernel(const float* __restrict__ Z, const float* __restrict__ Y) {
    extern __shared__ __align__(1024) char smem[];
    const uint32_t sb = smem_u32(smem);
    const int tid = threadIdx.x;
    const int bid = blockIdx.x;
    const int nit = (NT - bid + GRID - 1) / GRID;   // 27 or 28

    const int w = tid >> 5;
    const int l = tid & 31;
    const uint32_t mbase = (uint32_t)(w & 3) * 32u;
    const uint32_t nbase = (uint32_t)(w >> 2) * 64u;

    float acc[2][8][4];

    if (tid < 256) {
        // ---- consumers: LDSM + MMA ----
        const uint32_t sx    = (uint32_t)(l & 7);
        const uint32_t aoff  = (mbase + (uint32_t)(l & 15)) * 128u;
        const uint32_t chA   = (uint32_t)(l >> 4);
        const uint32_t boff  = (nbase + 8u * (uint32_t)(l >> 4) + (uint32_t)(l & 7)) * 128u;
        const uint32_t chB   = (uint32_t)((l >> 3) & 1);

#pragma unroll
        for (int mt = 0; mt < 2; ++mt)
#pragma unroll
            for (int nt = 0; nt < 8; ++nt)
#pragma unroll
                for (int c = 0; c < 4; ++c) acc[mt][nt][c] = 0.f;

        for (int it = 0; it < nit; ++it) {
            const int b = it & 1;
            BAR_SYNC(1 + b);                         // wait buffer filled
            const uint32_t stb = sb + (uint32_t)b * STAGE;
#pragma unroll
            for (int ks = 0; ks < 4; ++ks) {
                const uint32_t swA = 16u * (((uint32_t)(2 * ks) + chA) ^ sx);
                const uint32_t swB = 16u * (((uint32_t)(2 * ks) + chB) ^ sx);
                uint32_t ah0[4], ah1[4], al0[4], al1[4];
                ldsm4(ah0, stb + aoff + swA);
                ldsm4(ah1, stb + aoff + 2048u + swA);
                ldsm4(al0, stb + TILE + aoff + swA);
                ldsm4(al1, stb + TILE + aoff + 2048u + swA);
#pragma unroll
                for (int j = 0; j < 4; ++j) {
                    uint32_t bh[4], bl[4];
                    ldsm4(bh, stb + 2 * TILE + boff + (uint32_t)j * 2048u + swB);
                    ldsm4(bl, stb + 3 * TILE + boff + (uint32_t)j * 2048u + swB);
                    // interleaved across 4 accumulators; per-acc order preserved
                    // (ah*bh, then al*bh, then ah*bl) -> bitwise-identical sums
                    mma_bf16(acc[0][2 * j],     ah0, bh);
                    mma_bf16(acc[0][2 * j + 1], ah0, bh + 2);
                    mma_bf16(acc[1][2 * j],     ah1, bh);
                    mma_bf16(acc[1][2 * j + 1], ah1, bh + 2);
                    mma_bf16(acc[0][2 * j],     al0, bh);
                    mma_bf16(acc[0][2 * j + 1], al0, bh + 2);
                    mma_bf16(acc[1][2 * j],     al1, bh);
                    mma_bf16(acc[1][2 * j + 1], al1, bh + 2);
                    mma_bf16(acc[0][2 * j],     ah0, bl);
                    mma_bf16(acc[0][2 * j + 1], ah0, bl + 2);
                    mma_bf16(acc[1][2 * j],     ah1, bl);
                    mma_bf16(acc[1][2 * j + 1], ah1, bl + 2);
                }
            }
            BAR_ARRIVE(3 + b);                       // buffer consumed
        }
    } else {
        // ---- producers: LDG + convert + STS + norms ----
        const int ptid = tid - 256;
        const int r0v  = ptid >> 4;          // 0..15
        const int c8   = ptid & 15;
        const uint32_t cvt_base = (uint32_t)r0v * 128u
                                + 16u * ((uint32_t)(c8 >> 1) ^ (uint32_t)(r0v & 7))
                                + 8u * (uint32_t)(c8 & 1);

        const float4* zb = reinterpret_cast<const float4*>(Z) + (size_t)r0v * (DDIM / 4) + c8;
        const float4* yb = reinterpret_cast<const float4*>(Y) + (size_t)r0v * (DDIM / 4) + c8;

        float az[8], ay[8];
#pragma unroll
        for (int k = 0; k < 8; ++k) { az[k] = 0.f; ay[k] = 0.f; }

        float4 vz[8], vy[8];
        int t = bid;
#pragma unroll
        for (int k = 0; k < 8; ++k) {
            size_t o = (size_t)k * 16 * (DDIM / 4) + (size_t)t * 16;
            vz[k] = zb[o]; vy[k] = yb[o];
        }

        for (int it = 0; it < nit; ++it) {
            const int b = it & 1;
            if (it >= 2) BAR_SYNC(3 + b);            // wait buffer free
            char* st = smem + b * STAGE;
#pragma unroll
            for (int k = 0; k < 8; ++k) {
                uint32_t so = cvt_base + (uint32_t)k * 2048u;
                split_store(vz[k], st,            st + TILE,     so, az[k]);  // Ahi, Alo
                split_store(vy[k], st + 2 * TILE, st + 3 * TILE, so, ay[k]);  // Bhi, Blo
            }
            BAR_ARRIVE(1 + b);                       // buffer filled
            const int tn = t + GRID;
            if (it + 1 < nit) {
#pragma unroll
                for (int k = 0; k < 8; ++k) {
                    size_t o = (size_t)k * 16 * (DDIM / 4) + (size_t)tn * 16;
                    vz[k] = zb[o]; vy[k] = yb[o];
                }
            }
            t = tn;
        }

        // norm partials: 16-lane row-slice reduction, layout [c][row]
#pragma unroll
        for (int k = 0; k < 8; ++k) {
            float a = az[k], c = ay[k];
#pragma unroll
            for (int m = 1; m < 16; m <<= 1) {
                a += __shfl_xor_sync(0xFFFFFFFFu, a, m);
                c += __shfl_xor_sync(0xFFFFFFFFu, c, m);
            }
            if ((l & 15) == 0) {
                int row = r0v + (k << 4);
                g_xn2p[bid * BB + row] = a;
                g_yn2p[bid * BB + row] = c;
            }
        }
    }

    // ---- epilogue: stage acc in smem, write TRANSPOSED partial coalesced ----
    __syncthreads();                                  // stages dead; reuse smem
    float* sf = reinterpret_cast<float*>(smem);       // [128][129]
    if (tid < 256) {
        const int g  = l >> 2;
        const int t2 = (l & 3) * 2;
#pragma unroll
        for (int mt = 0; mt < 2; ++mt)
#pragma unroll
            for (int nt = 0; nt < 8; ++nt) {
                int m = (int)mbase + 16 * mt + g;
                int n = (int)nbase + 8 * nt + t2;
                sf[m * 129 + n]       = acc[mt][nt][0];
                sf[m * 129 + n + 1]   = acc[mt][nt][1];
                sf[(m + 8) * 129 + n]     = acc[mt][nt][2];
                sf[(m + 8) * 129 + n + 1] = acc[mt][nt][3];
            }
    }
    __syncthreads();
    float* gp = g_part + (size_t)bid * (BB * BB);
    for (int idx = tid; idx < BB * BB; idx += NTH) {
        int n = idx >> 7, m = idx & 127;              // gp[n*128+m] = dots[m][n] (m=Z,n=Y)
        gp[idx] = sf[m * 129 + n];
    }
}

// -------- reduce + finalize, fully parallel (128 CTAs), deterministic --------
__global__ void __launch_bounds__(512, 1)
reduce_finalize_kernel(float* __restrict__ out) {
    __shared__ float sd[4][BB];
    __shared__ float sxp[4][BB];
    __shared__ float syp[4][BB];
    __shared__ float sdot[BB];
    __shared__ float sxn[BB];
    __shared__ float syn2[BB];
    __shared__ int scnt[2];

    const int i = blockIdx.x;          // sim.T row (Y index)
    const int m = threadIdx.x & 127;   // column (Z index)
    const int q = threadIdx.x >> 7;    // 0..3; 148 = 4*37
    if (threadIdx.x == 0) { scnt[0] = 0; scnt[1] = 0; }

    float s = 0.f, a = 0.f, b = 0.f;
    const int c0 = q * 37;
#pragma unroll 4
    for (int c = c0; c < c0 + 37; ++c) {
        s += g_part[(size_t)c * (BB * BB) + i * BB + m];   // coalesced: m contiguous
        a += g_xn2p[c * BB + m];
        b += g_yn2p[c * BB + m];
    }
    sd[q][m] = s; sxp[q][m] = a; syp[q][m] = b;
    __syncthreads();

    if (q == 0) {
        sdot[m] = (sd[0][m] + sd[1][m]) + (sd[2][m] + sd[3][m]);
        sxn[m]  = sqrtf((sxp[0][m] + sxp[1][m]) + (sxp[2][m] + sxp[3][m]));
        syn2[m] = (syp[0][m] + syp[1][m]) + (syp[2][m] + syp[3][m]);
    }
    __syncthreads();

    if (q == 0) {
        const float yni = sqrtf(syn2[i]);
        const float d   = sdot[i] / fmaxf(sxn[i] * yni, 1e-8f);
        const float smv = sdot[m] / fmaxf(sxn[m] * yni, 1e-8f);
        int gt = (smv > d) ? 1 : 0;
        int eq = (smv == d && m < i) ? 1 : 0;    // stable tie-break: lower index wins
        unsigned bgt = __ballot_sync(0xFFFFFFFFu, gt != 0);
        unsigned beq = __ballot_sync(0xFFFFFFFFu, eq != 0);
        if ((threadIdx.x & 31) == 0) {
            atomicAdd(&scnt[0], __popc(bgt));
            atomicAdd(&scnt[1], __popc(beq));
        }
    }
    __syncthreads();

    if (threadIdx.x == 0) {
        const int rank = scnt[0] + scnt[1];
        const unsigned add = (1u << 20) | ((rank < 10 ? 1u : 0u) << 10) | (rank == 0 ? 1u : 0u);
        const unsigned old = atomicAdd(&g_pack, add);
        if ((old >> 20) == (unsigned)(BB - 1)) {     // last CTA finalizes
            const unsigned tot = old + add;
            out[0] = (float)(tot & 1023u) / (float)BB;
            out[1] = (float)((tot >> 10) & 1023u) / (float)BB;
            g_pack = 0;                              // reset for next graph replay
        }
    }
}

extern "C" void kernel_launch(void* const* d_in, const int* in_sizes, int n_in,
                              void* d_out, int out_size) {
    const float* Z = (const float*)d_in[0];
    const float* Y = (const float*)d_in[1];
    float* out = (float*)d_out;
    cudaFuncSetAttribute(gemm_kernel, cudaFuncAttributeMaxDynamicSharedMemorySize, SMEM_BYTES);
    gemm_kernel<<<GRID, NTH, SMEM_BYTES>>>(Z, Y);
    reduce_finalize_kernel<<<BB, 512>>>(out);
}